// round 1
// baseline (speedup 1.0000x reference)
#include <cuda_runtime.h>
#include <math.h>

// Problem dims (fixed by setup_inputs)
#define BATCH 256
#define DM    512
#define NN    1024
#define KTOT  (2*NN)        // concat [cos_sum | sin_sum] along K

// Phase-1 tiling
#define BT 16               // batch tile
#define NT 16               // neuron tile
#define DC 128              // d-chunk
#define P1_THREADS 256

// Phase-2 tiling (split-K SGEMM)
#define BM 64               // batch rows per block
#define BN 64               // out features per block
#define BK 16
#define SPLITK 8
#define KCHUNK (KTOT / SPLITK)   // 256

// Scratch (static device globals — no allocation allowed)
__device__ float g_sums[BATCH * KTOT];            // [b][k]: k<NN = cos_sum, k>=NN = sin_sum (2 MB)
__device__ float g_part[SPLITK * BATCH * DM];     // split-K partials (4 MB)

// ---------------------------------------------------------------------------
// Phase 1: resonance sums.
// One thread per (b, n) pair within a 16x16 tile; d processed in chunks of 128
// staged through shared memory. theta = x * (1/(1+|W|)) + B ; accumulate
// sin/cos via MUFU. 1024 blocks x 256 threads.
// ---------------------------------------------------------------------------
__global__ void __launch_bounds__(P1_THREADS) phase1_kernel(
    const float* __restrict__ xr, const float* __restrict__ xi,
    const float* __restrict__ W,  const float* __restrict__ Bm)
{
    __shared__ float xs[BT][DC + 1];   // pad -> stride 129, conflict-free on [tb][d]
    __shared__ float ws[NT][DC + 1];
    __shared__ float bs[NT][DC + 1];

    const int t  = threadIdx.x;
    const int tb = t & 15;             // batch row within tile
    const int tn = t >> 4;             // neuron within tile
    const int b0 = blockIdx.y * BT;
    const int n0 = blockIdx.x * NT;

    float accS = 0.0f, accC = 0.0f;

    for (int d0 = 0; d0 < DM; d0 += DC) {
        // Cooperative staging: 16x128 per array, 8 elems per thread each.
        #pragma unroll
        for (int i = t; i < BT * DC; i += P1_THREADS) {
            const int r = i >> 7;        // row within tile
            const int c = i & (DC - 1);  // column within chunk
            const int gx = (b0 + r) * DM + d0 + c;
            xs[r][c] = xr[gx] + xi[gx];
            const int gw = (n0 + r) * DM + d0 + c;
            const float wv = W[gw];
            ws[r][c] = __fdividef(1.0f, 1.0f + fabsf(wv));
            bs[r][c] = Bm[gw];
        }
        __syncthreads();

        #pragma unroll 16
        for (int d = 0; d < DC; d++) {
            const float th = fmaf(xs[tb][d], ws[tn][d], bs[tn][d]);
            float s, c;
            __sincosf(th, &s, &c);
            accS += s;
            accC += c;
        }
        __syncthreads();
    }

    g_sums[(b0 + tb) * KTOT + n0 + tn]       = accC;   // cos_sum
    g_sums[(b0 + tb) * KTOT + NN + n0 + tn]  = accS;   // sin_sum
}

// ---------------------------------------------------------------------------
// Phase 2: split-K SGEMM.  out[b][m] = sum_k A[b][k] * Wsel[m][k']
//   A = g_sums (256 x 2048); k < NN -> proj_cos_w, k >= NN -> proj_sin_w.
// Each block: 64x64 output tile over a 256-wide K slab; 4x4 per thread.
// Deterministic: writes to per-split partial buffer (no float atomics).
// Grid: (DM/BN=8, BATCH/BM=4, SPLITK=8) = 256 blocks x 256 threads.
// ---------------------------------------------------------------------------
__global__ void __launch_bounds__(256) phase2_kernel(
    const float* __restrict__ PC, const float* __restrict__ PS)
{
    __shared__ float As[BK][BM + 4];   // [k][b], row stride 68 floats (16B aligned)
    __shared__ float Bs[BK][BN + 4];   // [k][m]

    const int t  = threadIdx.x;
    const int tx = t & 15;             // -> 4 output columns (m)
    const int ty = t >> 4;             // -> 4 output rows (b)
    const int m0 = blockIdx.x * BN;
    const int b0 = blockIdx.y * BM;
    const int z  = blockIdx.z;
    const int kbase = z * KCHUNK;

    // Whole split chunk lies on one side of the cos/sin boundary (256 | 1024).
    const float* __restrict__ Wsel = (kbase < NN) ? PC : PS;
    const int koff = (kbase < NN) ? 0 : NN;

    float acc[4][4];
    #pragma unroll
    for (int i = 0; i < 4; i++)
        #pragma unroll
        for (int j = 0; j < 4; j++) acc[i][j] = 0.0f;

    for (int k0 = kbase; k0 < kbase + KCHUNK; k0 += BK) {
        #pragma unroll
        for (int i = t; i < BM * BK; i += 256) {
            const int r  = i >> 4;
            const int kk = i & 15;
            As[kk][r] = g_sums[(b0 + r) * KTOT + k0 + kk];
        }
        #pragma unroll
        for (int i = t; i < BN * BK; i += 256) {
            const int r  = i >> 4;
            const int kk = i & 15;
            Bs[kk][r] = Wsel[(m0 + r) * NN + (k0 + kk - koff)];
        }
        __syncthreads();

        #pragma unroll
        for (int kk = 0; kk < BK; kk++) {
            const float4 av = *(const float4*)&As[kk][ty * 4];
            const float4 bv = *(const float4*)&Bs[kk][tx * 4];
            const float a[4] = {av.x, av.y, av.z, av.w};
            const float b[4] = {bv.x, bv.y, bv.z, bv.w};
            #pragma unroll
            for (int i = 0; i < 4; i++)
                #pragma unroll
                for (int j = 0; j < 4; j++)
                    acc[i][j] = fmaf(a[i], b[j], acc[i][j]);
        }
        __syncthreads();
    }

    float* outp = &g_part[z * BATCH * DM];
    #pragma unroll
    for (int i = 0; i < 4; i++)
        #pragma unroll
        for (int j = 0; j < 4; j++)
            outp[(b0 + ty * 4 + i) * DM + m0 + tx * 4 + j] = acc[i][j];
}

// ---------------------------------------------------------------------------
// Phase 3: reduce split-K partials + SiLU.
// ---------------------------------------------------------------------------
__global__ void __launch_bounds__(256) phase3_kernel(float* __restrict__ out)
{
    const int i = blockIdx.x * 256 + threadIdx.x;
    if (i >= BATCH * DM) return;
    float v = 0.0f;
    #pragma unroll
    for (int zz = 0; zz < SPLITK; zz++)
        v += g_part[zz * BATCH * DM + i];
    out[i] = v / (1.0f + __expf(-v));   // silu
}

extern "C" void kernel_launch(void* const* d_in, const int* in_sizes, int n_in,
                              void* d_out, int out_size)
{
    (void)in_sizes; (void)n_in; (void)out_size;
    const float* xr = (const float*)d_in[0];
    const float* xi = (const float*)d_in[1];
    const float* W  = (const float*)d_in[2];
    const float* Bm = (const float*)d_in[3];
    const float* PC = (const float*)d_in[4];
    const float* PS = (const float*)d_in[5];
    float* out = (float*)d_out;

    dim3 g1(NN / NT, BATCH / BT);              // 64 x 16 = 1024 blocks
    phase1_kernel<<<g1, P1_THREADS>>>(xr, xi, W, Bm);

    dim3 g2(DM / BN, BATCH / BM, SPLITK);      // 8 x 4 x 8 = 256 blocks
    phase2_kernel<<<g2, 256>>>(PC, PS);

    phase3_kernel<<<(BATCH * DM + 255) / 256, 256>>>(out);
}